// round 1
// baseline (speedup 1.0000x reference)
#include <cuda_runtime.h>
#include <math.h>

// Problem constants
#define NATOM 50000
#define MNBR  12
#define AFEA  128
#define NBRF  64
#define NM    (NATOM*MNBR)     // 600000
#define C2A   256
#define EPSV  1e-5f
#define ROWTILES (NM/64)       // 9375

// ---------------- scratch (device globals; no allocations allowed) ----------
__device__ float g_P1[NATOM*C2A];              // atom @ W1   (50000x256)
__device__ float g_P2[NATOM*C2A];              // atom @ W2   (50000x256)
__device__ float g_gated[NM*C2A];              // 600000x256  (614 MB)
__device__ float g_psum[ROWTILES*C2A];         // per-rowtile masked col sums
__device__ float g_psq [ROWTILES*C2A];         // per-rowtile masked col sumsq
__device__ float g_ns[NATOM*AFEA];             // nbr_sumed   (50000x128)
__device__ float g_colsum[C2A];
__device__ float g_colsq[C2A];
__device__ float g_cnt;
__device__ float g_scale1[C2A], g_shift1[C2A];
__device__ float g_scale2[AFEA], g_shift2[AFEA];

// ---------------- K1: P1 = atom@W[0:128], P2 = atom@W[128:256] --------------
// Tiled SGEMM: BM=BN=64, BK=16, 256 threads, 4x4 per-thread microtile.
__global__ __launch_bounds__(256) void gemm_p12(const float* __restrict__ atom,
                                                const float* __restrict__ W) {
    const int bx = blockIdx.x;        // row tile
    const int by = blockIdx.y;        // col tile (0..3)
    const int z  = blockIdx.z;        // 0 -> P1, 1 -> P2
    const float* B = W + z * 128 * C2A;
    float* Cout = z ? g_P2 : g_P1;

    __shared__ float As[16 * 65];     // [k][m], pitch 65
    __shared__ float Bs[16 * 64];     // [k][n]

    const int tid = threadIdx.x;
    const int tx = tid & 15, ty = tid >> 4;
    const int row0 = bx * 64;

    float acc[4][4] = {};

    for (int k0 = 0; k0 < 128; k0 += 16) {
        #pragma unroll
        for (int i = 0; i < 4; i++) {                  // load A tile 64x16
            int e = tid + i * 256;
            int ar = e >> 4, ac = e & 15;
            int gr = row0 + ar;
            float v = (gr < NATOM) ? atom[gr * 128 + k0 + ac] : 0.f;
            As[ac * 65 + ar] = v;
        }
        #pragma unroll
        for (int i = 0; i < 4; i++) {                  // load B tile 16x64
            int e = tid + i * 256;
            int br = e >> 6, bc = e & 63;
            Bs[br * 64 + bc] = B[(k0 + br) * C2A + by * 64 + bc];
        }
        __syncthreads();
        #pragma unroll
        for (int k = 0; k < 16; k++) {
            float4 bv = *(const float4*)&Bs[k * 64 + tx * 4];
            float a0 = As[k * 65 + ty * 4 + 0];
            float a1 = As[k * 65 + ty * 4 + 1];
            float a2 = As[k * 65 + ty * 4 + 2];
            float a3 = As[k * 65 + ty * 4 + 3];
            acc[0][0] += a0 * bv.x; acc[0][1] += a0 * bv.y; acc[0][2] += a0 * bv.z; acc[0][3] += a0 * bv.w;
            acc[1][0] += a1 * bv.x; acc[1][1] += a1 * bv.y; acc[1][2] += a1 * bv.z; acc[1][3] += a1 * bv.w;
            acc[2][0] += a2 * bv.x; acc[2][1] += a2 * bv.y; acc[2][2] += a2 * bv.z; acc[2][3] += a2 * bv.w;
            acc[3][0] += a3 * bv.x; acc[3][1] += a3 * bv.y; acc[3][2] += a3 * bv.z; acc[3][3] += a3 * bv.w;
        }
        __syncthreads();
    }
    #pragma unroll
    for (int i = 0; i < 4; i++) {
        int gr = row0 + ty * 4 + i;
        if (gr < NATOM) {
            float4 v = make_float4(acc[i][0], acc[i][1], acc[i][2], acc[i][3]);
            *(float4*)&Cout[gr * C2A + by * 64 + tx * 4] = v;
        }
    }
}

// ---------------- K2: gated = nbr@W3 + bias + P1[n] + P2[idx]; masked stats -
// BM=BN=BK=64 (single K pass), 256 threads, 4x4 microtile.
__global__ __launch_bounds__(256) void gemm_gated(const float* __restrict__ nbr,
                                                  const float* __restrict__ W,
                                                  const float* __restrict__ bfc,
                                                  const int*   __restrict__ idx,
                                                  const float* __restrict__ mask) {
    const int bx = blockIdx.x;        // 0..9374
    const int by = blockIdx.y;        // 0..3
    const float* B = W + 256 * C2A;   // W3: rows 256..319

    __shared__ float As[64 * 65];     // [k][m], pitch 65
    __shared__ float Bs[64 * 64];     // [k][n]
    __shared__ float Red[16 * 64];

    const int tid = threadIdx.x;
    const int tx = tid & 15, ty = tid >> 4;
    const int row0 = bx * 64;

    #pragma unroll
    for (int i = 0; i < 16; i++) {                     // A tile 64x64
        int e = tid + i * 256;
        int ar = e >> 6, ac = e & 63;
        As[ac * 65 + ar] = nbr[(row0 + ar) * 64 + ac];
    }
    #pragma unroll
    for (int i = 0; i < 16; i++) {                     // B tile 64x64
        int e = tid + i * 256;
        int br = e >> 6, bc = e & 63;
        Bs[br * 64 + bc] = B[br * C2A + by * 64 + bc];
    }
    __syncthreads();

    float acc[4][4] = {};
    #pragma unroll
    for (int k = 0; k < 64; k++) {
        float4 bv = *(const float4*)&Bs[k * 64 + tx * 4];
        float a0 = As[k * 65 + ty * 4 + 0];
        float a1 = As[k * 65 + ty * 4 + 1];
        float a2 = As[k * 65 + ty * 4 + 2];
        float a3 = As[k * 65 + ty * 4 + 3];
        acc[0][0] += a0 * bv.x; acc[0][1] += a0 * bv.y; acc[0][2] += a0 * bv.z; acc[0][3] += a0 * bv.w;
        acc[1][0] += a1 * bv.x; acc[1][1] += a1 * bv.y; acc[1][2] += a1 * bv.z; acc[1][3] += a1 * bv.w;
        acc[2][0] += a2 * bv.x; acc[2][1] += a2 * bv.y; acc[2][2] += a2 * bv.z; acc[2][3] += a2 * bv.w;
        acc[3][0] += a3 * bv.x; acc[3][1] += a3 * bv.y; acc[3][2] += a3 * bv.z; acc[3][3] += a3 * bv.w;
    }

    // Epilogue: add bias + P1[n] + P2[idx[gr]], write gated, masked partials.
    float4 bias = *(const float4*)&bfc[by * 64 + tx * 4];
    float s[4] = {0, 0, 0, 0}, q[4] = {0, 0, 0, 0};
    #pragma unroll
    for (int i = 0; i < 4; i++) {
        int gr = row0 + ty * 4 + i;
        int n  = gr / MNBR;
        int nb = idx[gr];
        float mk = mask[gr];
        float4 p1 = *(const float4*)&g_P1[n  * C2A + by * 64 + tx * 4];
        float4 p2 = *(const float4*)&g_P2[nb * C2A + by * 64 + tx * 4];
        float4 v;
        v.x = acc[i][0] + bias.x + p1.x + p2.x;
        v.y = acc[i][1] + bias.y + p1.y + p2.y;
        v.z = acc[i][2] + bias.z + p1.z + p2.z;
        v.w = acc[i][3] + bias.w + p1.w + p2.w;
        *(float4*)&g_gated[(unsigned)gr * C2A + by * 64 + tx * 4] = v;
        s[0] += mk * v.x; q[0] += mk * v.x * v.x;
        s[1] += mk * v.y; q[1] += mk * v.y * v.y;
        s[2] += mk * v.z; q[2] += mk * v.z * v.z;
        s[3] += mk * v.w; q[3] += mk * v.w * v.w;
    }

    __syncthreads();   // done with As/Bs usage region; Red is separate anyway
    // Tree-reduce s over the 16 thread rows (deterministic)
    #pragma unroll
    for (int j = 0; j < 4; j++) Red[ty * 64 + tx * 4 + j] = s[j];
    #pragma unroll
    for (int off = 8; off > 0; off >>= 1) {
        __syncthreads();
        if (ty < off) {
            #pragma unroll
            for (int j = 0; j < 4; j++)
                Red[ty * 64 + tx * 4 + j] += Red[(ty + off) * 64 + tx * 4 + j];
        }
    }
    __syncthreads();
    if (ty == 0) {
        #pragma unroll
        for (int j = 0; j < 4; j++)
            g_psum[bx * C2A + by * 64 + tx * 4 + j] = Red[tx * 4 + j];
    }
    __syncthreads();
    // Same for q
    #pragma unroll
    for (int j = 0; j < 4; j++) Red[ty * 64 + tx * 4 + j] = q[j];
    #pragma unroll
    for (int off = 8; off > 0; off >>= 1) {
        __syncthreads();
        if (ty < off) {
            #pragma unroll
            for (int j = 0; j < 4; j++)
                Red[ty * 64 + tx * 4 + j] += Red[(ty + off) * 64 + tx * 4 + j];
        }
    }
    __syncthreads();
    if (ty == 0) {
        #pragma unroll
        for (int j = 0; j < 4; j++)
            g_psq[bx * C2A + by * 64 + tx * 4 + j] = Red[tx * 4 + j];
    }
}

// ---------------- K3: reduce partials -> column sums; also cnt --------------
__global__ __launch_bounds__(256) void reduce1(const float* __restrict__ mask) {
    __shared__ float sm[256];
    const int b = blockIdx.x, tid = threadIdx.x;
    float s = 0.f;
    if (b < 256) {
        for (int i = tid; i < ROWTILES; i += 256) s += g_psum[i * C2A + b];
    } else if (b < 512) {
        int c = b - 256;
        for (int i = tid; i < ROWTILES; i += 256) s += g_psq[i * C2A + c];
    } else {
        for (int i = tid; i < NM; i += 256) s += mask[i];
    }
    sm[tid] = s; __syncthreads();
    for (int off = 128; off > 0; off >>= 1) {
        if (tid < off) sm[tid] += sm[tid + off];
        __syncthreads();
    }
    if (tid == 0) {
        if (b < 256)      g_colsum[b] = sm[0];
        else if (b < 512) g_colsq[b - 256] = sm[0];
        else              g_cnt = sm[0];
    }
}

// ---------------- K4: finalize BN1 affine --------------------------------
__global__ void finalize1(const float* __restrict__ gamma1,
                          const float* __restrict__ beta1) {
    int c = threadIdx.x;
    float cnt  = g_cnt;
    float mean = g_colsum[c] / cnt;
    float var  = g_colsq[c] / cnt - mean * mean;
    float sc   = rsqrtf(var + EPSV) * gamma1[c];
    g_scale1[c] = sc;
    g_shift1[c] = beta1[c] - mean * sc;
}

// ---------------- K5: nbr_sumed[n,c] = sum_m mask*sig(f)*softplus(g) --------
__global__ __launch_bounds__(128) void gate_sum(const float* __restrict__ mask) {
    const int n = blockIdx.x;
    const int c = threadIdx.x;
    const float sc_f = g_scale1[c],       sh_f = g_shift1[c];
    const float sc_c = g_scale1[c + 128], sh_c = g_shift1[c + 128];
    float acc = 0.f;
    #pragma unroll
    for (int m = 0; m < MNBR; m++) {
        float mk = mask[n * MNBR + m];        // uniform across block
        if (mk != 0.0f) {
            unsigned base = (unsigned)(n * MNBR + m) * C2A;
            float f = g_gated[base + c]       * sc_f + sh_f;
            float g = g_gated[base + 128 + c] * sc_c + sh_c;
            float sig = 1.f / (1.f + expf(-f));
            float sp  = fmaxf(g, 0.f) + log1pf(expf(-fabsf(g)));
            acc += mk * sig * sp;
        }
    }
    g_ns[n * AFEA + c] = acc;
}

// ---------------- K6: BN2 stats + affine (one block per column) -------------
__global__ __launch_bounds__(256) void reduce2(const float* __restrict__ gamma2,
                                               const float* __restrict__ beta2) {
    __shared__ float ss[256], sq[256];
    const int c = blockIdx.x, tid = threadIdx.x;
    float s = 0.f, q = 0.f;
    for (int r = tid; r < NATOM; r += 256) {
        float v = g_ns[r * AFEA + c];
        s += v; q += v * v;
    }
    ss[tid] = s; sq[tid] = q; __syncthreads();
    for (int off = 128; off > 0; off >>= 1) {
        if (tid < off) { ss[tid] += ss[tid + off]; sq[tid] += sq[tid + off]; }
        __syncthreads();
    }
    if (tid == 0) {
        float mean = ss[0] / (float)NATOM;
        float var  = sq[0] / (float)NATOM - mean * mean;
        float sc   = rsqrtf(var + EPSV) * gamma2[c];
        g_scale2[c] = sc;
        g_shift2[c] = beta2[c] - mean * sc;
    }
}

// ---------------- K7: out = softplus(atom + BN2(nbr_sumed)) -----------------
__global__ __launch_bounds__(256) void out_k(const float* __restrict__ atom,
                                             float* __restrict__ out) {
    int i = blockIdx.x * 256 + threadIdx.x;
    if (i < NATOM * AFEA) {
        int c = i & 127;
        float v = atom[i] + g_ns[i] * g_scale2[c] + g_shift2[c];
        out[i] = fmaxf(v, 0.f) + log1pf(expf(-fabsf(v)));
    }
}

// ---------------- launch ----------------------------------------------------
extern "C" void kernel_launch(void* const* d_in, const int* in_sizes, int n_in,
                              void* d_out, int out_size) {
    const float* atom  = (const float*)d_in[0];   // (50000,128)
    const float* nbr   = (const float*)d_in[1];   // (50000,12,64)
    const int*   idx   = (const int*)  d_in[2];   // (50000,12)
    const float* mask  = (const float*)d_in[3];   // (50000,12)
    const float* W     = (const float*)d_in[4];   // (320,256)
    const float* bfc   = (const float*)d_in[5];   // (256)
    const float* g1    = (const float*)d_in[6];
    const float* b1    = (const float*)d_in[7];
    const float* g2    = (const float*)d_in[8];
    const float* b2    = (const float*)d_in[9];
    float* out = (float*)d_out;

    gemm_p12 <<<dim3((NATOM + 63) / 64, 4, 2), 256>>>(atom, W);
    gemm_gated<<<dim3(ROWTILES, 4), 256>>>(nbr, W, bfc, idx, mask);
    reduce1  <<<513, 256>>>(mask);
    finalize1<<<1, 256>>>(g1, b1);
    gate_sum <<<NATOM, 128>>>(mask);
    reduce2  <<<AFEA, 256>>>(g2, b2);
    out_k    <<<(NATOM * AFEA + 255) / 256, 256>>>(atom, out);
}

// round 2
// speedup vs baseline: 1.1618x; 1.1618x over previous
#include <cuda_runtime.h>
#include <cuda_bf16.h>
#include <math.h>
#include <stdint.h>

// Problem constants
#define NATOM 50000
#define MNBR  12
#define AFEA  128
#define NBRF  64
#define NM    (NATOM*MNBR)     // 600000
#define C2A   256
#define EPSV  1e-5f
#define GTILES (NM/96)         // 6250 row tiles of 96 (= 8 atoms)

// ---------------- scratch (device globals) ----------------------------------
__device__ float g_P1[(size_t)NATOM*C2A];
__device__ float g_P2[(size_t)NATOM*C2A];
__device__ float g_gated[(size_t)NM*C2A];
__device__ float g_psum[(size_t)GTILES*C2A];
__device__ float g_psq [(size_t)GTILES*C2A];
__device__ float g_ns[NATOM*AFEA];
__device__ float g_colsum[C2A];
__device__ float g_colsq[C2A];
__device__ float g_cnt;
__device__ float g_scale1[C2A], g_shift1[C2A];
__device__ float g_scale2[AFEA], g_shift2[AFEA];

// ---------------- bf16 split + mma helpers ----------------------------------
__device__ __forceinline__ void bsplit(float x, __nv_bfloat16& h, __nv_bfloat16& l) {
    h = __float2bfloat16(x);
    l = __float2bfloat16(x - __bfloat162float(h));
}

// D += A(16x16 bf16) * B(16x8 bf16), fp32 accumulate.
__device__ __forceinline__ void mma_bf16(float* c, const uint32_t* a,
                                         uint32_t b0, uint32_t b1) {
    asm volatile(
        "mma.sync.aligned.m16n8k16.row.col.f32.bf16.bf16.f32 "
        "{%0,%1,%2,%3}, {%4,%5,%6,%7}, {%8,%9}, {%0,%1,%2,%3};\n"
        : "+f"(c[0]), "+f"(c[1]), "+f"(c[2]), "+f"(c[3])
        : "r"(a[0]), "r"(a[1]), "r"(a[2]), "r"(a[3]), "r"(b0), "r"(b1));
}

// ---------------- K1: P1 = atom@W[0:128], P2 = atom@W[128:256] (tensor) -----
// Tile 128 rows x 64 cols, grid.y in 0..7 selects which 64-col slice of the
// 512-wide [P1|P2] output. K=128 in 4 chunks of 32. 256 threads = 8 warps.
#define PA2 40    // smem pitch (bf16 elems): (20g+tig)%32 all distinct -> conflict-free
__global__ __launch_bounds__(256) void gemm_p12_tc(const float* __restrict__ atom,
                                                   const float* __restrict__ W) {
    __shared__ __align__(16) __nv_bfloat16 Ahi[128*PA2], Alo[128*PA2];
    __shared__ __align__(16) __nv_bfloat16 Bhi[64*PA2],  Blo[64*PA2];

    const int tid = threadIdx.x;
    const int bx = blockIdx.x, by = blockIdx.y;
    const int w = tid >> 5, lane = tid & 31, g = lane >> 2, tig = lane & 3;

    const float* Bsrc = W + (by >= 4 ? 128*C2A : 0) + (by & 3)*64;
    float* Cdst = (by >= 4) ? g_P2 : g_P1;
    const int cb = (by & 3) * 64;

    float acc[8][4];
    #pragma unroll
    for (int j = 0; j < 8; j++) { acc[j][0]=0.f; acc[j][1]=0.f; acc[j][2]=0.f; acc[j][3]=0.f; }

    for (int kc = 0; kc < 4; kc++) {
        __syncthreads();
        // A chunk 128x32 (guarded)
        for (int i = tid; i < 128*32; i += 256) {
            int r = i >> 5, c = i & 31;
            int gr = bx*128 + r;
            float x = (gr < NATOM) ? atom[(size_t)gr*128 + kc*32 + c] : 0.f;
            bsplit(x, Ahi[r*PA2 + c], Alo[r*PA2 + c]);
        }
        // B chunk 32x64, stored transposed [n][k]
        for (int i = tid; i < 32*64; i += 256) {
            int k = i >> 6, n = i & 63;
            float x = Bsrc[(size_t)(kc*32 + k)*C2A + n];
            bsplit(x, Bhi[n*PA2 + k], Blo[n*PA2 + k]);
        }
        __syncthreads();

        #pragma unroll
        for (int ks = 0; ks < 2; ks++) {
            const int k0 = ks * 16;
            const int r0 = (w*16 + g) * PA2, r1 = (w*16 + g + 8) * PA2;
            uint32_t ah[4], al[4];
            ah[0] = *(const uint32_t*)&Ahi[r0 + k0 + 2*tig];
            ah[1] = *(const uint32_t*)&Ahi[r1 + k0 + 2*tig];
            ah[2] = *(const uint32_t*)&Ahi[r0 + k0 + 8 + 2*tig];
            ah[3] = *(const uint32_t*)&Ahi[r1 + k0 + 8 + 2*tig];
            al[0] = *(const uint32_t*)&Alo[r0 + k0 + 2*tig];
            al[1] = *(const uint32_t*)&Alo[r1 + k0 + 2*tig];
            al[2] = *(const uint32_t*)&Alo[r0 + k0 + 8 + 2*tig];
            al[3] = *(const uint32_t*)&Alo[r1 + k0 + 8 + 2*tig];
            #pragma unroll
            for (int j = 0; j < 8; j++) {
                const int nb = (j*8 + g) * PA2;
                uint32_t bh0 = *(const uint32_t*)&Bhi[nb + k0 + 2*tig];
                uint32_t bh1 = *(const uint32_t*)&Bhi[nb + k0 + 8 + 2*tig];
                uint32_t bl0 = *(const uint32_t*)&Blo[nb + k0 + 2*tig];
                uint32_t bl1 = *(const uint32_t*)&Blo[nb + k0 + 8 + 2*tig];
                mma_bf16(acc[j], ah, bh0, bh1);
                mma_bf16(acc[j], ah, bl0, bl1);
                mma_bf16(acc[j], al, bh0, bh1);
            }
        }
    }

    // Epilogue: direct fragment stores (32B sectors fully used)
    const int gr0 = bx*128 + w*16 + g;
    const int gr1 = gr0 + 8;
    #pragma unroll
    for (int j = 0; j < 8; j++) {
        const int c = cb + j*8 + 2*tig;
        if (gr0 < NATOM)
            *(float2*)&Cdst[(size_t)gr0*C2A + c] = make_float2(acc[j][0], acc[j][1]);
        if (gr1 < NATOM)
            *(float2*)&Cdst[(size_t)gr1*C2A + c] = make_float2(acc[j][2], acc[j][3]);
    }
}

// ---------------- K2: gated = nbr@W3 + b + P1[n] + P2[idx]; masked stats ----
// Tile 96 rows (8 atoms) x full 256 cols (internal by-loop). 192 threads = 6 warps.
#define PA 72   // (4g+tig)%32 all distinct -> conflict-free
__global__ __launch_bounds__(192) void gemm_gated_tc(const float* __restrict__ nbr,
                                                     const float* __restrict__ W,
                                                     const float* __restrict__ bfc,
                                                     const int*   __restrict__ idx,
                                                     const float* __restrict__ mask) {
    __shared__ __align__(16) __nv_bfloat16 Ahi[96*PA], Alo[96*PA];
    __shared__ __align__(16) __nv_bfloat16 Bhi[64*PA], Blo[64*PA];
    __shared__ float SRed[6*64];

    const int tid = threadIdx.x;
    const int bx = blockIdx.x;
    const int w = tid >> 5, lane = tid & 31, g = lane >> 2, tig = lane & 3;
    const float* W3 = W + 256*C2A;

    // Load A tile 96x64 once, split hi/lo
    for (int i = tid; i < 96*64/4; i += 192) {
        int r = i >> 4, c4 = (i & 15) * 4;
        float4 v = *(const float4*)&nbr[((size_t)bx*96 + r)*64 + c4];
        bsplit(v.x, Ahi[r*PA + c4 + 0], Alo[r*PA + c4 + 0]);
        bsplit(v.y, Ahi[r*PA + c4 + 1], Alo[r*PA + c4 + 1]);
        bsplit(v.z, Ahi[r*PA + c4 + 2], Alo[r*PA + c4 + 2]);
        bsplit(v.w, Ahi[r*PA + c4 + 3], Alo[r*PA + c4 + 3]);
    }

    // Per-thread row metadata (rows w*16+g and +8)
    const int gr0 = bx*96 + w*16 + g;
    const int gr1 = gr0 + 8;
    const int n0 = gr0 / MNBR, n1 = gr1 / MNBR;
    const int nb0 = idx[gr0], nb1 = idx[gr1];
    const float mk0 = mask[gr0], mk1 = mask[gr1];

    for (int by = 0; by < 4; by++) {
        __syncthreads();   // Bs/SRed free from previous iteration; A visible
        // Load B slice 64x64, stored transposed [n][k]
        for (int i = tid; i < 64*64; i += 192) {
            int k = i >> 6, n = i & 63;
            float x = W3[(size_t)k*C2A + by*64 + n];
            bsplit(x, Bhi[n*PA + k], Blo[n*PA + k]);
        }
        __syncthreads();

        float acc[8][4];
        #pragma unroll
        for (int j = 0; j < 8; j++) { acc[j][0]=0.f; acc[j][1]=0.f; acc[j][2]=0.f; acc[j][3]=0.f; }

        #pragma unroll
        for (int ks = 0; ks < 4; ks++) {
            const int k0 = ks * 16;
            const int r0 = (w*16 + g) * PA, r1 = (w*16 + g + 8) * PA;
            uint32_t ah[4], al[4];
            ah[0] = *(const uint32_t*)&Ahi[r0 + k0 + 2*tig];
            ah[1] = *(const uint32_t*)&Ahi[r1 + k0 + 2*tig];
            ah[2] = *(const uint32_t*)&Ahi[r0 + k0 + 8 + 2*tig];
            ah[3] = *(const uint32_t*)&Ahi[r1 + k0 + 8 + 2*tig];
            al[0] = *(const uint32_t*)&Alo[r0 + k0 + 2*tig];
            al[1] = *(const uint32_t*)&Alo[r1 + k0 + 2*tig];
            al[2] = *(const uint32_t*)&Alo[r0 + k0 + 8 + 2*tig];
            al[3] = *(const uint32_t*)&Alo[r1 + k0 + 8 + 2*tig];
            #pragma unroll
            for (int j = 0; j < 8; j++) {
                const int nb = (j*8 + g) * PA;
                uint32_t bh0 = *(const uint32_t*)&Bhi[nb + k0 + 2*tig];
                uint32_t bh1 = *(const uint32_t*)&Bhi[nb + k0 + 8 + 2*tig];
                uint32_t bl0 = *(const uint32_t*)&Blo[nb + k0 + 2*tig];
                uint32_t bl1 = *(const uint32_t*)&Blo[nb + k0 + 8 + 2*tig];
                mma_bf16(acc[j], ah, bh0, bh1);
                mma_bf16(acc[j], ah, bl0, bl1);
                mma_bf16(acc[j], al, bh0, bh1);
            }
        }

        // Epilogue: add bias + P1[n] + P2[idx], write gated, masked stats.
        const int byc = by * 64;
        float s16[16], q16[16];
        #pragma unroll
        for (int t = 0; t < 16; t++) { s16[t] = 0.f; q16[t] = 0.f; }

        #pragma unroll
        for (int j = 0; j < 8; j++) {
            const int c = byc + j*8 + 2*tig;
            float2 bb  = *(const float2*)&bfc[c];
            float2 p10 = *(const float2*)&g_P1[(size_t)n0*C2A + c];
            float2 p20 = *(const float2*)&g_P2[(size_t)nb0*C2A + c];
            float v00 = acc[j][0] + bb.x + p10.x + p20.x;
            float v01 = acc[j][1] + bb.y + p10.y + p20.y;
            *(float2*)&g_gated[(size_t)gr0*C2A + c] = make_float2(v00, v01);
            float2 p11 = *(const float2*)&g_P1[(size_t)n1*C2A + c];
            float2 p21 = *(const float2*)&g_P2[(size_t)nb1*C2A + c];
            float v10 = acc[j][2] + bb.x + p11.x + p21.x;
            float v11 = acc[j][3] + bb.y + p11.y + p21.y;
            *(float2*)&g_gated[(size_t)gr1*C2A + c] = make_float2(v10, v11);
            s16[2*j]   += mk0*v00 + mk1*v10;
            s16[2*j+1] += mk0*v01 + mk1*v11;
            q16[2*j]   += mk0*v00*v00 + mk1*v10*v10;
            q16[2*j+1] += mk0*v01*v01 + mk1*v11*v11;
        }

        // Reduce over g within warp (deterministic butterfly over lane bits 2..4)
        #pragma unroll
        for (int t = 0; t < 16; t++) {
            #pragma unroll
            for (int off = 4; off <= 16; off <<= 1) {
                s16[t] += __shfl_xor_sync(0xffffffffu, s16[t], off);
                q16[t] += __shfl_xor_sync(0xffffffffu, q16[t], off);
            }
        }
        // Cross-warp: sums first
        if (lane < 4) {
            #pragma unroll
            for (int j = 0; j < 8; j++) {
                SRed[w*64 + j*8 + 2*lane + 0] = s16[2*j];
                SRed[w*64 + j*8 + 2*lane + 1] = s16[2*j+1];
            }
        }
        __syncthreads();
        if (tid < 64) {
            float t = 0.f;
            #pragma unroll
            for (int w2 = 0; w2 < 6; w2++) t += SRed[w2*64 + tid];
            g_psum[(size_t)bx*C2A + byc + tid] = t;
        }
        __syncthreads();
        if (lane < 4) {
            #pragma unroll
            for (int j = 0; j < 8; j++) {
                SRed[w*64 + j*8 + 2*lane + 0] = q16[2*j];
                SRed[w*64 + j*8 + 2*lane + 1] = q16[2*j+1];
            }
        }
        __syncthreads();
        if (tid < 64) {
            float t = 0.f;
            #pragma unroll
            for (int w2 = 0; w2 < 6; w2++) t += SRed[w2*64 + tid];
            g_psq[(size_t)bx*C2A + byc + tid] = t;
        }
    }
}

// ---------------- K3: reduce partials -> column sums; also cnt --------------
__global__ __launch_bounds__(256) void reduce1(const float* __restrict__ mask) {
    __shared__ float sm[256];
    const int b = blockIdx.x, tid = threadIdx.x;
    float s = 0.f;
    if (b < 256) {
        for (int i = tid; i < GTILES; i += 256) s += g_psum[(size_t)i * C2A + b];
    } else if (b < 512) {
        int c = b - 256;
        for (int i = tid; i < GTILES; i += 256) s += g_psq[(size_t)i * C2A + c];
    } else {
        for (int i = tid; i < NM; i += 256) s += mask[i];
    }
    sm[tid] = s; __syncthreads();
    for (int off = 128; off > 0; off >>= 1) {
        if (tid < off) sm[tid] += sm[tid + off];
        __syncthreads();
    }
    if (tid == 0) {
        if (b < 256)      g_colsum[b] = sm[0];
        else if (b < 512) g_colsq[b - 256] = sm[0];
        else              g_cnt = sm[0];
    }
}

// ---------------- K4: finalize BN1 affine -----------------------------------
__global__ void finalize1(const float* __restrict__ gamma1,
                          const float* __restrict__ beta1) {
    int c = threadIdx.x;
    float cnt  = g_cnt;
    float mean = g_colsum[c] / cnt;
    float var  = g_colsq[c] / cnt - mean * mean;
    float sc   = rsqrtf(var + EPSV) * gamma1[c];
    g_scale1[c] = sc;
    g_shift1[c] = beta1[c] - mean * sc;
}

// ---------------- K5: nbr_sumed[n,c] = sum_m mask*sig(f)*softplus(g) --------
__global__ __launch_bounds__(128) void gate_sum(const float* __restrict__ mask) {
    const int n = blockIdx.x;
    const int c = threadIdx.x;
    const float sc_f = g_scale1[c],       sh_f = g_shift1[c];
    const float sc_c = g_scale1[c + 128], sh_c = g_shift1[c + 128];
    float acc = 0.f;
    #pragma unroll
    for (int m = 0; m < MNBR; m++) {
        float mk = mask[n * MNBR + m];        // uniform across block
        if (mk != 0.0f) {
            size_t base = (size_t)(n * MNBR + m) * C2A;
            float f = g_gated[base + c]       * sc_f + sh_f;
            float gg = g_gated[base + 128 + c] * sc_c + sh_c;
            float sig = 1.f / (1.f + expf(-f));
            float sp  = fmaxf(gg, 0.f) + log1pf(expf(-fabsf(gg)));
            acc += mk * sig * sp;
        }
    }
    g_ns[n * AFEA + c] = acc;
}

// ---------------- K6: BN2 stats + affine (one block per column) -------------
__global__ __launch_bounds__(256) void reduce2(const float* __restrict__ gamma2,
                                               const float* __restrict__ beta2) {
    __shared__ float ss[256], sq[256];
    const int c = blockIdx.x, tid = threadIdx.x;
    float s = 0.f, q = 0.f;
    for (int r = tid; r < NATOM; r += 256) {
        float v = g_ns[r * AFEA + c];
        s += v; q += v * v;
    }
    ss[tid] = s; sq[tid] = q; __syncthreads();
    for (int off = 128; off > 0; off >>= 1) {
        if (tid < off) { ss[tid] += ss[tid + off]; sq[tid] += sq[tid + off]; }
        __syncthreads();
    }
    if (tid == 0) {
        float mean = ss[0] / (float)NATOM;
        float var  = sq[0] / (float)NATOM - mean * mean;
        float sc   = rsqrtf(var + EPSV) * gamma2[c];
        g_scale2[c] = sc;
        g_shift2[c] = beta2[c] - mean * sc;
    }
}

// ---------------- K7: out = softplus(atom + BN2(nbr_sumed)) -----------------
__global__ __launch_bounds__(256) void out_k(const float* __restrict__ atom,
                                             float* __restrict__ out) {
    int i = blockIdx.x * 256 + threadIdx.x;
    if (i < NATOM * AFEA) {
        int c = i & 127;
        float v = atom[i] + g_ns[i] * g_scale2[c] + g_shift2[c];
        out[i] = fmaxf(v, 0.f) + log1pf(expf(-fabsf(v)));
    }
}

// ---------------- launch ----------------------------------------------------
extern "C" void kernel_launch(void* const* d_in, const int* in_sizes, int n_in,
                              void* d_out, int out_size) {
    const float* atom  = (const float*)d_in[0];   // (50000,128)
    const float* nbr   = (const float*)d_in[1];   // (50000,12,64)
    const int*   idx   = (const int*)  d_in[2];   // (50000,12)
    const float* mask  = (const float*)d_in[3];   // (50000,12)
    const float* W     = (const float*)d_in[4];   // (320,256)
    const float* bfc   = (const float*)d_in[5];   // (256)
    const float* g1    = (const float*)d_in[6];
    const float* b1    = (const float*)d_in[7];
    const float* g2    = (const float*)d_in[8];
    const float* b2    = (const float*)d_in[9];
    float* out = (float*)d_out;

    gemm_p12_tc  <<<dim3((NATOM + 127) / 128, 8), 256>>>(atom, W);
    gemm_gated_tc<<<GTILES, 192>>>(nbr, W, bfc, idx, mask);
    reduce1      <<<513, 256>>>(mask);
    finalize1    <<<1, 256>>>(g1, b1);
    gate_sum     <<<NATOM, 128>>>(mask);
    reduce2      <<<AFEA, 256>>>(g2, b2);
    out_k        <<<(NATOM * AFEA + 255) / 256, 256>>>(atom, out);
}